// round 12
// baseline (speedup 1.0000x reference)
#include <cuda_runtime.h>
#include <cuda_bf16.h>
#include <cstdint>

// ---------------- problem constants ----------------
namespace {
constexpr int B   = 2048;
constexpr int NN  = 24;
constexpr int NC  = 8;
constexpr int D   = 512;
constexpr int NH  = 8;
constexpr int L   = 3;
constexpr int FH  = 1024;
constexpr int S   = 33;
constexpr int DH  = 64;
constexpr int M   = B * S;      // 67584
constexpr int NQKV = 3 * D;     // 1536

// bf16 weight planes (O, F2 only), per-layer: O[512][512] | F2[1024][512], [K][N]
constexpr size_t W_O     = (size_t)D * D;
constexpr size_t W_F2    = (size_t)FH * D;
constexpr size_t OFF16_F2 = W_O;
constexpr size_t W16_LSTR = W_O + W_F2;
constexpr size_t W16_TOT  = 3 * W16_LSTR;

// int8 weight planes (QKV + F1 interleaved), [N][K] layout. per-layer N = 3584
constexpr int    W8N     = NQKV + 2 * FH;   // 3584
constexpr int    OFF8_F1 = NQKV;            // col offset of F1 region
constexpr size_t W8_TOT  = (size_t)L * W8N * D;

// bf16 GEMM smem (BM=128 BN=128 BK=32, 3 stages)
constexpr int A_STRIDE = 40;
constexpr int B_STRIDE = 136;
constexpr int A_PLANE  = 128 * A_STRIDE;
constexpr int B_PLANE  = 32 * B_STRIDE;
constexpr uint32_t ST_AL = (uint32_t)A_PLANE * 2;
constexpr uint32_t ST_BH = 2u * A_PLANE * 2;
constexpr uint32_t ST_BL = 2u * A_PLANE * 2 + B_PLANE * 2;
constexpr uint32_t STAGE_BYTES = 2u * (A_PLANE + B_PLANE) * 2; // 37888
constexpr size_t GEMM_SMEM = 3 * (size_t)STAGE_BYTES;

// int8 GEMM smem (BM=128 BN=64 BK=32, 3 stages), stride 48B conflict-free
constexpr uint32_t S8_AB = 6144;    // A digit-b plane offset (128*48)
constexpr uint32_t S8_BA = 12288;   // B digit-a
constexpr uint32_t S8_BB = 15360;   // B digit-b (64*48 later)
constexpr uint32_t STAGE8 = 18432;
constexpr size_t GEMM8_SMEM = 3 * (size_t)STAGE8;   // 55296

constexpr int EPI_PLAIN = 0;
constexpr int EPI_RES   = 1;
constexpr int EPI_REGLU = 2;
}

// ---------------- scratch ----------------
__device__ float g_X[(size_t)M * D];
__device__ float g_QKV[(size_t)M * NQKV];
__device__ float g_bqkv[L * NQKV];
__device__ signed char g_A8a[(size_t)M * D];     // LN out int8 digit0
__device__ signed char g_A8b[(size_t)M * D];     // digit1
__device__ float g_sA[M];                        // LN row scales
__device__ signed char g_W8a[W8_TOT];            // weights [N][K] digit0
__device__ signed char g_W8b[W8_TOT];
__device__ float g_sW[L * W8N];                  // weight col scales
__device__ uint16_t g_OH[(size_t)M * D];
__device__ uint16_t g_OL[(size_t)M * D];
__device__ uint16_t g_UH[(size_t)M * FH];
__device__ uint16_t g_UL[(size_t)M * FH];
__device__ uint16_t g_WH[W16_TOT];
__device__ uint16_t g_WL[W16_TOT];
__device__ unsigned char g_mask[L * S * S];
__device__ int g_cnt[L * S];
__device__ int g_rs[L * S];
__device__ unsigned char g_fi[L * S * S];
__device__ unsigned char g_fj[L * S * S];
__device__ int g_T[L];

// ---------------- helpers ----------------
__device__ __forceinline__ void split2(float x, float y, uint32_t& hi, uint32_t& lo)
{
    __nv_bfloat162 h = __floats2bfloat162_rn(x, y);
    float hx = __bfloat162float(h.x), hy = __bfloat162float(h.y);
    __nv_bfloat162 l = __floats2bfloat162_rn(x - hx, y - hy);
    hi = *reinterpret_cast<uint32_t*>(&h);
    lo = *reinterpret_cast<uint32_t*>(&l);
}

__device__ __forceinline__ void split1(float x, uint16_t& hi, uint16_t& lo)
{
    __nv_bfloat16 h = __float2bfloat16(x);
    float hf = __bfloat162float(h);
    __nv_bfloat16 l = __float2bfloat16(x - hf);
    hi = *reinterpret_cast<uint16_t*>(&h);
    lo = *reinterpret_cast<uint16_t*>(&l);
}

__device__ __forceinline__ void ldmx4(uint32_t addr, uint32_t& r0, uint32_t& r1,
                                      uint32_t& r2, uint32_t& r3)
{
    asm volatile("ldmatrix.sync.aligned.m8n8.x4.shared.b16 {%0,%1,%2,%3},[%4];"
                 : "=r"(r0), "=r"(r1), "=r"(r2), "=r"(r3) : "r"(addr));
}

__device__ __forceinline__ void ldmx4t(uint32_t addr, uint32_t& r0, uint32_t& r1,
                                       uint32_t& r2, uint32_t& r3)
{
    asm volatile("ldmatrix.sync.aligned.m8n8.x4.trans.shared.b16 {%0,%1,%2,%3},[%4];"
                 : "=r"(r0), "=r"(r1), "=r"(r2), "=r"(r3) : "r"(addr));
}

__device__ __forceinline__ void mma16(float* c, const uint32_t* a, const uint32_t* b)
{
    asm volatile(
        "mma.sync.aligned.m16n8k16.row.col.f32.bf16.bf16.f32 "
        "{%0,%1,%2,%3},{%4,%5,%6,%7},{%8,%9},{%0,%1,%2,%3};\n"
        : "+f"(c[0]), "+f"(c[1]), "+f"(c[2]), "+f"(c[3])
        : "r"(a[0]), "r"(a[1]), "r"(a[2]), "r"(a[3]),
          "r"(b[0]), "r"(b[1]));
}

__device__ __forceinline__ void mma8i(int* c, const uint32_t* a, const uint32_t* b)
{
    asm volatile(
        "mma.sync.aligned.m16n8k32.row.col.s32.s8.s8.s32 "
        "{%0,%1,%2,%3},{%4,%5,%6,%7},{%8,%9},{%0,%1,%2,%3};\n"
        : "+r"(c[0]), "+r"(c[1]), "+r"(c[2]), "+r"(c[3])
        : "r"(a[0]), "r"(a[1]), "r"(a[2]), "r"(a[3]),
          "r"(b[0]), "r"(b[1]));
}

__device__ __forceinline__ uint32_t lds32(uint32_t addr)
{
    uint32_t v;
    asm volatile("ld.shared.b32 %0,[%1];" : "=r"(v) : "r"(addr));
    return v;
}

__device__ __forceinline__ void cpasync16(uint32_t dst, const void* src) {
    asm volatile("cp.async.cg.shared.global [%0], [%1], 16;" :: "r"(dst), "l"(src));
}

__device__ __forceinline__ void quant4(float4 v, float inv, uint32_t& d0, uint32_t& d1)
{
    int q0 = __float2int_rn(v.x * inv);
    int q1 = __float2int_rn(v.y * inv);
    int q2 = __float2int_rn(v.z * inv);
    int q3 = __float2int_rn(v.w * inv);
    int e0 = __float2int_rn(127.0f * (v.x * inv - (float)q0));
    int e1 = __float2int_rn(127.0f * (v.y * inv - (float)q1));
    int e2 = __float2int_rn(127.0f * (v.z * inv - (float)q2));
    int e3 = __float2int_rn(127.0f * (v.w * inv - (float)q3));
    d0 = (q0 & 0xff) | ((q1 & 0xff) << 8) | ((q2 & 0xff) << 16) | ((q3 & 0xff) << 24);
    d1 = (e0 & 0xff) | ((e1 & 0xff) << 8) | ((e2 & 0xff) << 16) | ((e3 & 0xff) << 24);
}

// ---------------- mask canonicalization ----------------
__global__ void mask_convert_kernel(const unsigned char* __restrict__ raw)
{
    int i = blockIdx.x * blockDim.x + threadIdx.x;
    if (i >= L * S * S) return;
    bool v;
    if (raw[34] == 1)            v = raw[i] != 0;
    else if (raw[3] == 0x3f)     v = ((const float*)raw)[i] != 0.0f;
    else                         v = ((const int*)raw)[i] != 0;
    g_mask[i] = v ? 1 : 0;
}

// ---------------- CSR build ----------------
__global__ void csr_build_kernel()
{
    int l = threadIdx.x;
    if (l >= L) return;
    const unsigned char* m = g_mask + l * S * S;
    int pos = 0;
    for (int i = 0; i < S; ++i) {
        g_rs[l * S + i] = pos;
        int c = 0;
        for (int j = 0; j < S; ++j) {
            if (m[i * S + j]) {
                g_fi[l * S * S + pos] = (unsigned char)i;
                g_fj[l * S * S + pos] = (unsigned char)j;
                ++pos; ++c;
            }
        }
        g_cnt[l * S + i] = c;
    }
    g_T[l] = pos;
}

// ---------------- qkv bias pack ----------------
__global__ void biaspack_kernel(const float* __restrict__ bq, const float* __restrict__ bk,
                                const float* __restrict__ bv)
{
    int i = blockIdx.x * blockDim.x + threadIdx.x;
    if (i >= L * NQKV) return;
    int l = i / NQKV, c = i % NQKV;
    float v = (c < D) ? bq[l * D + c] : (c < 2 * D) ? bk[l * D + c - D] : bv[l * D + c - 2 * D];
    g_bqkv[i] = v;
}

// ---------------- tokenizer ----------------
__global__ void tokenize_kernel(const float* __restrict__ x_num,
                                const int* __restrict__ x_cat,
                                const float* __restrict__ w_num,
                                const float* __restrict__ b_num,
                                const float* __restrict__ emb_cat,
                                const float* __restrict__ b_cat,
                                const float* __restrict__ cls,
                                const int* __restrict__ cat_offsets)
{
    int idx = blockIdx.x * blockDim.x + threadIdx.x;
    const int total = M * (D / 4);
    if (idx >= total) return;
    int d4 = idx & (D / 4 - 1);
    int ms = idx >> 7;
    int s  = ms % S;
    int b  = ms / S;
    int d  = d4 * 4;
    float4 o;
    if (s < NN) {
        float xv  = x_num[b * NN + s];
        float4 w  = *(const float4*)(w_num + (size_t)s * D + d);
        float4 bb = *(const float4*)(b_num + (size_t)s * D + d);
        o.x = xv * w.x + bb.x;
        o.y = xv * w.y + bb.y;
        o.z = xv * w.z + bb.z;
        o.w = xv * w.w + bb.w;
    } else if (s < NN + NC) {
        int c   = s - NN;
        int row = x_cat[b * NC + c] + cat_offsets[c];
        float4 e  = *(const float4*)(emb_cat + (size_t)row * D + d);
        float4 bb = *(const float4*)(b_cat + (size_t)c * D + d);
        o.x = e.x + bb.x; o.y = e.y + bb.y; o.z = e.z + bb.z; o.w = e.w + bb.w;
    } else {
        o = *(const float4*)(cls + d);
    }
    *(float4*)(g_X + (size_t)ms * D + d) = o;
}

// ---------------- bf16 weight split (O + F2 only), [K][N] ----------------
__global__ void wsplit16_kernel(const float* __restrict__ Wo, const float* __restrict__ Wf2)
{
    size_t idx = (size_t)blockIdx.x * blockDim.x + threadIdx.x;
    const size_t total = L * W16_LSTR / 4;
    if (idx >= total) return;
    size_t d0 = idx * 4;
    int l = (int)(d0 / W16_LSTR);
    size_t o = d0 - (size_t)l * W16_LSTR;
    float4 vv;
    if (o < W_O) {
        vv = *(const float4*)(Wo + (size_t)l * W_O + o);
    } else {
        vv = *(const float4*)(Wf2 + (size_t)l * W_F2 + (o - W_O));
    }
    uint32_t h0, l0, h1, l1;
    split2(vv.x, vv.y, h0, l0);
    split2(vv.z, vv.w, h1, l1);
    *(uint2*)(g_WH + d0) = make_uint2(h0, h1);
    *(uint2*)(g_WL + d0) = make_uint2(l0, l1);
}

// ---------------- int8 weight column scales (warp per dst column) ----------------
__global__ void wcolscale_kernel(const float* __restrict__ Wq, const float* __restrict__ Wk,
                                 const float* __restrict__ Wv, const float* __restrict__ Wf1)
{
    int col = blockIdx.x * 8 + (threadIdx.x >> 5);   // global dst col
    int lane = threadIdx.x & 31;
    if (col >= L * W8N) return;
    int l = col / W8N, c = col % W8N;
    const float* src; int scol; size_t rowstride;
    if (c < NQKV) {
        src = (c < D) ? Wq : (c < 2 * D) ? Wk : Wv;
        src += (size_t)l * D * D;
        scol = c & (D - 1);
        rowstride = D;
    } else {
        int ci = c - NQKV;
        int j = ci >> 1;
        scol = (ci & 1) ? FH + j : j;
        src = Wf1 + (size_t)l * D * (2 * FH);
        rowstride = 2 * FH;
    }
    float m = 0.0f;
    for (int k = lane; k < D; k += 32)
        m = fmaxf(m, fabsf(src[(size_t)k * rowstride + scol]));
#pragma unroll
    for (int o = 16; o > 0; o >>= 1)
        m = fmaxf(m, __shfl_xor_sync(0xffffffffu, m, o));
    if (lane == 0) g_sW[col] = fmaxf(m, 1e-30f);
}

// ---------------- int8 weight quantize into [N][K] ----------------
__global__ void wsplit8_kernel(const float* __restrict__ Wq, const float* __restrict__ Wk,
                               const float* __restrict__ Wv, const float* __restrict__ Wf1)
{
    size_t idx = (size_t)blockIdx.x * blockDim.x + threadIdx.x;   // quads
    const size_t total = W8_TOT / 4;
    if (idx >= total) return;
    size_t t = idx * 4;
    int col = (int)(t / D);          // global dst col
    int k0  = (int)(t % D);
    int l = col / W8N, c = col % W8N;
    const float* src; int scol; size_t rowstride;
    if (c < NQKV) {
        src = (c < D) ? Wq : (c < 2 * D) ? Wk : Wv;
        src += (size_t)l * D * D;
        scol = c & (D - 1);
        rowstride = D;
    } else {
        int ci = c - NQKV;
        int j = ci >> 1;
        scol = (ci & 1) ? FH + j : j;
        src = Wf1 + (size_t)l * D * (2 * FH);
        rowstride = 2 * FH;
    }
    float inv = 127.0f / g_sW[col];
    float4 v;
    v.x = src[(size_t)(k0 + 0) * rowstride + scol];
    v.y = src[(size_t)(k0 + 1) * rowstride + scol];
    v.z = src[(size_t)(k0 + 2) * rowstride + scol];
    v.w = src[(size_t)(k0 + 3) * rowstride + scol];
    uint32_t d0, d1;
    quant4(v, inv, d0, d1);
    *(uint32_t*)(g_W8a + t) = d0;
    *(uint32_t*)(g_W8b + t) = d1;
}

// ---------------- LayerNorm (warp per row) -> int8 digits + row scale ----------------
__global__ void ln_quant_kernel(const float* __restrict__ X,
                                const float* __restrict__ w, const float* __restrict__ bb)
{
    int warp = threadIdx.x >> 5;
    int lane = threadIdx.x & 31;
    int row  = blockIdx.x * 8 + warp;
    const float* xr = X + (size_t)row * D;
    float4 v[4];
    float s = 0.0f, sq = 0.0f;
#pragma unroll
    for (int c = 0; c < 4; ++c) {
        v[c] = *(const float4*)(xr + c * 128 + lane * 4);
        s  += v[c].x + v[c].y + v[c].z + v[c].w;
        sq += v[c].x * v[c].x + v[c].y * v[c].y + v[c].z * v[c].z + v[c].w * v[c].w;
    }
#pragma unroll
    for (int o = 16; o > 0; o >>= 1) {
        s  += __shfl_xor_sync(0xffffffffu, s, o);
        sq += __shfl_xor_sync(0xffffffffu, sq, o);
    }
    float mean = s * (1.0f / D);
    float var  = sq * (1.0f / D) - mean * mean;
    float r = rsqrtf(var + 1e-5f);
    float4 o[4];
    float mx = 0.0f;
#pragma unroll
    for (int c = 0; c < 4; ++c) {
        int col = c * 128 + lane * 4;
        float4 wv = *(const float4*)(w + col);
        float4 bv = *(const float4*)(bb + col);
        o[c].x = (v[c].x - mean) * r * wv.x + bv.x;
        o[c].y = (v[c].y - mean) * r * wv.y + bv.y;
        o[c].z = (v[c].z - mean) * r * wv.z + bv.z;
        o[c].w = (v[c].w - mean) * r * wv.w + bv.w;
        mx = fmaxf(mx, fmaxf(fmaxf(fabsf(o[c].x), fabsf(o[c].y)),
                             fmaxf(fabsf(o[c].z), fabsf(o[c].w))));
    }
#pragma unroll
    for (int oo = 16; oo > 0; oo >>= 1)
        mx = fmaxf(mx, __shfl_xor_sync(0xffffffffu, mx, oo));
    mx = fmaxf(mx, 1e-30f);
    if (lane == 0) g_sA[row] = mx;
    float inv = 127.0f / mx;
#pragma unroll
    for (int c = 0; c < 4; ++c) {
        int col = c * 128 + lane * 4;
        uint32_t d0, d1;
        quant4(o[c], inv, d0, d1);
        size_t off = (size_t)row * D + col;
        *(uint32_t*)(g_A8a + off) = d0;
        *(uint32_t*)(g_A8b + off) = d1;
    }
}

// ---------------- int8 2-digit tensor-core GEMM ----------------
// C = (sA sB /127^2)(acc0 + accX/127) + bias [+ reglu]. BM=128 BN=64 BK=32.
// 256 threads, 8 warps as 2(m) x 4(n), warp tile 64x16. 3-stage cp.async.
template <int EPI>
__global__ void __launch_bounds__(256, 2)
gemm8_kernel(const signed char* __restrict__ A8a, const signed char* __restrict__ A8b,
             const float* __restrict__ sA,
             const signed char* __restrict__ W8a, const signed char* __restrict__ W8b,
             const float* __restrict__ sW,
             const float* __restrict__ bias,
             float* __restrict__ C, uint16_t* __restrict__ UH, uint16_t* __restrict__ UL,
             int N)
{
    extern __shared__ signed char sm8[];
    const uint32_t shBase = (uint32_t)__cvta_generic_to_shared(sm8);

    const int tid  = threadIdx.x;
    const int lane = tid & 31;
    const int warp = tid >> 5;
    const int wm   = (warp & 1) * 64;
    const int wn   = (warp >> 1) * 16;
    const int grp  = lane >> 2;
    const int t4   = lane & 3;

    const int bm = blockIdx.x;
    const int bn = blockIdx.y;
    constexpr int KT = D / 32;   // 16

    int acc0[4][2][4], accX[4][2][4];
#pragma unroll
    for (int i = 0; i < 4; ++i)
#pragma unroll
        for (int j = 0; j < 2; ++j)
#pragma unroll
            for (int r = 0; r < 4; ++r) { acc0[i][j][r] = 0; accX[i][j][r] = 0; }

    const int ar = tid >> 1;            // A row 0..127
    const int ph = (tid & 1) * 16;      // 16B phase
    const int bnr = (tid & 127) >> 1;   // B row 0..63 (tid<128)

    auto load_tile = [&](int kt, int st) {
        const uint32_t sb = shBase + (uint32_t)st * STAGE8;
        {
            uint32_t dst = sb + (uint32_t)(ar * 48) + ph;
            size_t src = (size_t)(bm * 128 + ar) * D + kt * 32 + ph;
            cpasync16(dst,         A8a + src);
            cpasync16(dst + S8_AB, A8b + src);
        }
        if (tid < 128) {
            uint32_t dst = sb + S8_BA + (uint32_t)(bnr * 48) + ph;
            size_t src = (size_t)(bn * 64 + bnr) * D + kt * 32 + ph;
            cpasync16(dst,                   W8a + src);
            cpasync16(dst + (S8_BB - S8_BA), W8b + src);
        }
        asm volatile("cp.async.commit_group;" ::: "memory");
    };

    const uint32_t aBase = shBase + (uint32_t)((wm + grp) * 48 + 4 * t4);
    const uint32_t bBase = shBase + S8_BA + (uint32_t)((wn + grp) * 48 + 4 * t4);

    load_tile(0, 0);
    load_tile(1, 1);

    for (int kt = 0; kt < KT; ++kt) {
        const int st = kt % 3;
        if (kt + 1 < KT) asm volatile("cp.async.wait_group 1;" ::: "memory");
        else             asm volatile("cp.async.wait_group 0;" ::: "memory");
        __syncthreads();
        if (kt + 2 < KT) load_tile(kt + 2, (kt + 2) % 3);

        const uint32_t aSt = aBase + (uint32_t)st * STAGE8;
        const uint32_t bSt = bBase + (uint32_t)st * STAGE8;

        uint32_t a0[4][4], a1[4][4], b0[2][2], b1[2][2];
#pragma unroll
        for (int mi = 0; mi < 4; ++mi) {
            uint32_t ad = aSt + mi * (16 * 48);
            a0[mi][0] = lds32(ad);
            a0[mi][1] = lds32(ad + 8 * 48);
            a0[mi][2] = lds32(ad + 16);
            a0[mi][3] = lds32(ad + 8 * 48 + 16);
            a1[mi][0] = lds32(ad + S8_AB);
            a1[mi][1] = lds32(ad + S8_AB + 8 * 48);
            a1[mi][2] = lds32(ad + S8_AB + 16);
            a1[mi][3] = lds32(ad + S8_AB + 8 * 48 + 16);
        }
#pragma unroll
        for (int ni = 0; ni < 2; ++ni) {
            uint32_t bd = bSt + ni * (8 * 48);
            b0[ni][0] = lds32(bd);
            b0[ni][1] = lds32(bd + 16);
            b1[ni][0] = lds32(bd + (S8_BB - S8_BA));
            b1[ni][1] = lds32(bd + (S8_BB - S8_BA) + 16);
        }
#pragma unroll
        for (int mi = 0; mi < 4; ++mi)
#pragma unroll
            for (int ni = 0; ni < 2; ++ni)
                mma8i(acc0[mi][ni], a0[mi], b0[ni]);
#pragma unroll
        for (int mi = 0; mi < 4; ++mi)
#pragma unroll
            for (int ni = 0; ni < 2; ++ni)
                mma8i(accX[mi][ni], a0[mi], b1[ni]);
#pragma unroll
        for (int mi = 0; mi < 4; ++mi)
#pragma unroll
            for (int ni = 0; ni < 2; ++ni)
                mma8i(accX[mi][ni], a1[mi], b0[ni]);
    }

    // epilogue
    const float i127   = 1.0f / 127.0f;
    const float i16129 = 1.0f / 16129.0f;
#pragma unroll
    for (int mi = 0; mi < 4; ++mi) {
        int r0 = bm * 128 + wm + mi * 16 + grp;
        float sa0 = sA[r0] * i16129;
        float sa1 = sA[r0 + 8] * i16129;
#pragma unroll
        for (int ni = 0; ni < 2; ++ni) {
            int c0 = bn * 64 + wn + ni * 8 + 2 * t4;
            float sb0 = sW[c0], sb1 = sW[c0 + 1];
            float v0 = sa0 * sb0 * ((float)acc0[mi][ni][0] + (float)accX[mi][ni][0] * i127);
            float v1 = sa0 * sb1 * ((float)acc0[mi][ni][1] + (float)accX[mi][ni][1] * i127);
            float v2 = sa1 * sb0 * ((float)acc0[mi][ni][2] + (float)accX[mi][ni][2] * i127);
            float v3 = sa1 * sb1 * ((float)acc0[mi][ni][3] + (float)accX[mi][ni][3] * i127);
            if (EPI == EPI_REGLU) {
                int j = c0 >> 1;
                float ba = bias[j], bg = bias[FH + j];
                float u0 = (v0 + ba) * fmaxf(v1 + bg, 0.0f);
                float u1 = (v2 + ba) * fmaxf(v3 + bg, 0.0f);
                uint16_t h, l;
                split1(u0, h, l);
                UH[(size_t)r0 * FH + j] = h;
                UL[(size_t)r0 * FH + j] = l;
                split1(u1, h, l);
                UH[(size_t)(r0 + 8) * FH + j] = h;
                UL[(size_t)(r0 + 8) * FH + j] = l;
            } else {
                float b0 = bias[c0], b1 = bias[c0 + 1];
                *(float2*)(C + (size_t)r0 * N + c0)       = make_float2(v0 + b0, v1 + b1);
                *(float2*)(C + (size_t)(r0 + 8) * N + c0) = make_float2(v2 + b0, v3 + b1);
            }
        }
    }
}

// ---------------- split-bf16 3-term GEMM (O, F2) ----------------
template <int EPI>
__global__ void __launch_bounds__(256, 2)
gemm_kernel(const uint16_t* __restrict__ AH, const uint16_t* __restrict__ AL,
            const uint16_t* __restrict__ BH, const uint16_t* __restrict__ BL,
            const float* __restrict__ bias, const float* __restrict__ Rsd,
            float* __restrict__ C, int K, int N)
{
    extern __shared__ uint16_t sm[];
    const uint32_t shBase = (uint32_t)__cvta_generic_to_shared(sm);

    const int tid  = threadIdx.x;
    const int lane = tid & 31;
    const int warp = tid >> 5;
    const int wm   = (warp & 1) * 64;
    const int wn   = (warp >> 1) * 32;
    const int grp  = lane >> 2;
    const int t4   = lane & 3;

    const int bm = blockIdx.x;
    const int bn = blockIdx.y;
    const int KT = K >> 5;

    float acc[4][4][4];
#pragma unroll
    for (int i = 0; i < 4; ++i)
#pragma unroll
        for (int j = 0; j < 4; ++j)
#pragma unroll
            for (int r = 0; r < 4; ++r) acc[i][j][r] = 0.0f;

    const int agr = tid >> 1;
    const int aco = (tid & 1) * 32;
    const int bgr = tid >> 3;
    const int bco = (tid & 7) * 32;

    auto load_tile = [&](int kt, int st) {
        const uint32_t sb = shBase + (uint32_t)st * STAGE_BYTES;
        {
            uint32_t doff = sb + (uint32_t)(agr * A_STRIDE) * 2 + aco;
            const uint16_t* sH = AH + (size_t)(bm * 128 + agr) * K + kt * 32 + (aco >> 1);
            const uint16_t* sL = AL + (size_t)(bm * 128 + agr) * K + kt * 32 + (aco >> 1);
            cpasync16(doff,               sH);
            cpasync16(doff + 16,          sH + 8);
            cpasync16(doff + ST_AL,       sL);
            cpasync16(doff + ST_AL + 16,  sL + 8);
        }
        {
            uint32_t doff = sb + ST_BH + (uint32_t)(bgr * B_STRIDE) * 2 + bco;
            const uint16_t* sH = BH + (size_t)(kt * 32 + bgr) * N + bn * 128 + (bco >> 1);
            const uint16_t* sL = BL + (size_t)(kt * 32 + bgr) * N + bn * 128 + (bco >> 1);
            cpasync16(doff,                         sH);
            cpasync16(doff + 16,                    sH + 8);
            cpasync16(doff + (ST_BL - ST_BH),       sL);
            cpasync16(doff + (ST_BL - ST_BH) + 16,  sL + 8);
        }
        asm volatile("cp.async.commit_group;" ::: "memory");
    };

    const int arowL = lane & 15;
    const int kofA  = (lane >> 4) * 8;
    const uint32_t aBase = shBase + (uint32_t)(((wm + arowL) * A_STRIDE + kofA) * 2);
    const int krowL = lane & 15;
    const int nofB  = (lane >> 4) * 8;
    const uint32_t bBase = shBase + ST_BH + (uint32_t)((krowL * B_STRIDE + wn + nofB) * 2);

    load_tile(0, 0);
    load_tile(1, 1);

    for (int kt = 0; kt < KT; ++kt) {
        const int st = kt % 3;
        if (kt + 1 < KT) asm volatile("cp.async.wait_group 1;" ::: "memory");
        else             asm volatile("cp.async.wait_group 0;" ::: "memory");
        __syncthreads();
        if (kt + 2 < KT) load_tile(kt + 2, (kt + 2) % 3);

        const uint32_t aSt = aBase + (uint32_t)st * STAGE_BYTES;
        const uint32_t bSt = bBase + (uint32_t)st * STAGE_BYTES;
#pragma unroll
        for (int ks = 0; ks < 2; ++ks) {
            uint32_t ah[4][4], al[4][4];
#pragma unroll
            for (int mi = 0; mi < 4; ++mi) {
                uint32_t ad = aSt + mi * (16 * A_STRIDE * 2) + ks * 32;
                ldmx4(ad, ah[mi][0], ah[mi][1], ah[mi][2], ah[mi][3]);
                ldmx4(ad + ST_AL, al[mi][0], al[mi][1], al[mi][2], al[mi][3]);
            }
#pragma unroll
            for (int pr = 0; pr < 2; ++pr) {
                uint32_t bh[2][2], bl[2][2];
                uint32_t bd = bSt + pr * 32 + ks * (16 * B_STRIDE * 2);
                ldmx4t(bd, bh[0][0], bh[0][1], bh[1][0], bh[1][1]);
                ldmx4t(bd + (ST_BL - ST_BH), bl[0][0], bl[0][1], bl[1][0], bl[1][1]);
#pragma unroll
                for (int mi = 0; mi < 4; ++mi)
#pragma unroll
                    for (int nj = 0; nj < 2; ++nj)
                        mma16(acc[mi][2 * pr + nj], al[mi], bh[nj]);
#pragma unroll
                for (int mi = 0; mi < 4; ++mi)
#pragma unroll
                    for (int nj = 0; nj < 2; ++nj)
                        mma16(acc[mi][2 * pr + nj], ah[mi], bl[nj]);
#pragma unroll
                for (int mi = 0; mi < 4; ++mi)
#pragma unroll
                    for (int nj = 0; nj < 2; ++nj)
                        mma16(acc[mi][2 * pr + nj], ah[mi], bh[nj]);
            }
        }
    }

#pragma unroll
    for (int mi = 0; mi < 4; ++mi) {
        int r0 = bm * 128 + wm + mi * 16 + grp;
#pragma unroll
        for (int ni = 0; ni < 4; ++ni) {
            int c0 = bn * 128 + wn + ni * 8 + 2 * t4;
            float b0 = bias[c0], b1 = bias[c0 + 1];
            float2 o0 = make_float2(acc[mi][ni][0] + b0, acc[mi][ni][1] + b1);
            float2 o1 = make_float2(acc[mi][ni][2] + b0, acc[mi][ni][3] + b1);
            if (EPI == EPI_RES) {
                float2 rv0 = *(const float2*)(Rsd + (size_t)r0 * N + c0);
                float2 rv1 = *(const float2*)(Rsd + (size_t)(r0 + 8) * N + c0);
                o0.x += rv0.x; o0.y += rv0.y;
                o1.x += rv1.x; o1.y += rv1.y;
            }
            *(float2*)(C + (size_t)r0 * N + c0)       = o0;
            *(float2*)(C + (size_t)(r0 + 8) * N + c0) = o1;
        }
    }
}

// ---------------- sparse attention ----------------
__global__ void attn_kernel(const float* __restrict__ QKV,
                            const int* __restrict__ cnt, const int* __restrict__ rs,
                            const unsigned char* __restrict__ fi,
                            const unsigned char* __restrict__ fj,
                            const int* __restrict__ Tp,
                            uint16_t* __restrict__ OH, uint16_t* __restrict__ OL)
{
    int bh = blockIdx.x;
    int h  = bh % NH;
    int b  = bh / NH;
    int t  = threadIdx.x;

    __shared__ float qs[S][DH + 1];
    __shared__ float ks[S][DH + 1];
    __shared__ float vs[S][DH + 1];
    __shared__ float fp[S * S];
    __shared__ unsigned char sfi[S * S], sfj[S * S];
    __shared__ int scnt[S], srs[S];

    const int T = *Tp;

    const size_t rbase = (size_t)(b * S) * NQKV + h * DH;
    for (int i = t; i < S * DH; i += 256) {
        int s = i / DH, d = i % DH;
        size_t p = rbase + (size_t)s * NQKV + d;
        qs[s][d] = QKV[p];
        ks[s][d] = QKV[p + D];
        vs[s][d] = QKV[p + 2 * D];
    }
    for (int p = t; p < T; p += 256) { sfi[p] = fi[p]; sfj[p] = fj[p]; }
    if (t < S) { scnt[t] = cnt[t]; srs[t] = rs[t]; }
    __syncthreads();

    const float scale = 0.125f;
    for (int p = t; p < T; p += 256) {
        int i = sfi[p], j = sfj[p];
        float s = 0.0f;
#pragma unroll 16
        for (int d = 0; d < DH; ++d) s += qs[i][d] * ks[j][d];
        fp[p] = s * scale;
    }
    __syncthreads();

    if (t < S) {
        int r0 = srs[t], c = scnt[t];
        float mx = -1e30f;
        for (int e = 0; e < c; ++e) mx = fmaxf(mx, fp[r0 + e]);
        float sum = 0.0f;
        for (int e = 0; e < c; ++e) { float ee = __expf(fp[r0 + e] - mx); fp[r0 + e] = ee; sum += ee; }
        float inv = 1.0f / sum;
        for (int e = 0; e < c; ++e) fp[r0 + e] *= inv;
    }
    __syncthreads();

    const size_t obase = (size_t)(b * S) * D + h * DH;
    for (int p = t; p < S * (DH / 2); p += 256) {
        int i  = p / (DH / 2);
        int dd = (p % (DH / 2)) * 2;
        int r0 = srs[i], c = scnt[i];
        float o0 = 0.0f, o1 = 0.0f;
        for (int e = 0; e < c; ++e) {
            int j = sfj[r0 + e];
            float a = fp[r0 + e];
            o0 += a * vs[j][dd];
            o1 += a * vs[j][dd + 1];
        }
        uint32_t hi, lo;
        split2(o0, o1, hi, lo);
        size_t off = obase + (size_t)i * D + dd;
        *(uint32_t*)(OH + off) = hi;
        *(uint32_t*)(OL + off) = lo;
    }
}

// ---------------- head ----------------
__global__ void head_kernel(const float* __restrict__ X,
                            const float* __restrict__ hw, const float* __restrict__ hb,
                            const float* __restrict__ Wh, const float* __restrict__ bh,
                            float* __restrict__ out)
{
    int b = blockIdx.x;
    int t = threadIdx.x;
    const float* xr = X + ((size_t)b * S + (S - 1)) * D;
    float4 v = *(const float4*)(xr + t * 4);
    float s  = v.x + v.y + v.z + v.w;
    float sq = v.x * v.x + v.y * v.y + v.z * v.z + v.w * v.w;
#pragma unroll
    for (int o = 16; o > 0; o >>= 1) {
        s  += __shfl_xor_sync(0xffffffffu, s, o);
        sq += __shfl_xor_sync(0xffffffffu, sq, o);
    }
    __shared__ float ss[4], sqs[4], ds[4];
    if ((t & 31) == 0) { ss[t >> 5] = s; sqs[t >> 5] = sq; }
    __syncthreads();
    s  = ss[0] + ss[1] + ss[2] + ss[3];
    sq = sqs[0] + sqs[1] + sqs[2] + sqs[3];
    float mean = s * (1.0f / D);
    float var  = sq * (1.0f / D) - mean * mean;
    float r = rsqrtf(var + 1e-5f);
    float4 wv = *(const float4*)(hw + t * 4);
    float4 bv = *(const float4*)(hb + t * 4);
    float4 wh = *(const float4*)(Wh + t * 4);
    float dot = 0.0f;
    dot += fmaxf((v.x - mean) * r * wv.x + bv.x, 0.0f) * wh.x;
    dot += fmaxf((v.y - mean) * r * wv.y + bv.y, 0.0f) * wh.y;
    dot += fmaxf((v.z - mean) * r * wv.z + bv.z, 0.0f) * wh.z;
    dot += fmaxf((v.w - mean) * r * wv.w + bv.w, 0.0f) * wh.w;
#pragma unroll
    for (int o = 16; o > 0; o >>= 1) dot += __shfl_xor_sync(0xffffffffu, dot, o);
    if ((t & 31) == 0) ds[t >> 5] = dot;
    __syncthreads();
    if (t == 0) out[b] = ds[0] + ds[1] + ds[2] + ds[3] + bh[0];
}

// ---------------- launcher ----------------
extern "C" void kernel_launch(void* const* d_in, const int* in_sizes, int n_in,
                              void* d_out, int out_size)
{
    (void)in_sizes; (void)n_in; (void)out_size;
    const float* x_num    = (const float*)d_in[0];
    const int*   x_cat    = (const int*)d_in[1];
    const float* w_num    = (const float*)d_in[2];
    const float* b_num    = (const float*)d_in[3];
    const float* emb_cat  = (const float*)d_in[4];
    const float* b_cat    = (const float*)d_in[5];
    const float* cls      = (const float*)d_in[6];
    const float* ln1_w    = (const float*)d_in[7];
    const float* ln1_b    = (const float*)d_in[8];
    const float* Wq       = (const float*)d_in[9];
    const float* bq       = (const float*)d_in[10];
    const float* Wk       = (const float*)d_in[11];
    const float* bk       = (const float*)d_in[12];
    const float* Wv       = (const float*)d_in[13];
    const float* bv       = (const float*)d_in[14];
    const float* Wo       = (const float*)d_in[15];
    const float* bo       = (const float*)d_in[16];
    const float* ln2_w    = (const float*)d_in[17];
    const float* ln2_b    = (const float*)d_in[18];
    const float* Wf1      = (const float*)d_in[19];
    const float* bf1      = (const float*)d_in[20];
    const float* Wf2      = (const float*)d_in[21];
    const float* bf2      = (const float*)d_in[22];
    const unsigned char* mask_raw = (const unsigned char*)d_in[23];
    const int*   cat_offsets  = (const int*)d_in[24];
    const float* hln_w    = (const float*)d_in[25];
    const float* hln_b    = (const float*)d_in[26];
    const float* Wh       = (const float*)d_in[27];
    const float* bh       = (const float*)d_in[28];
    float* out = (float*)d_out;

    float *X, *QKV, *BQKV, *SA, *SW;
    signed char *A8a, *A8b, *W8a, *W8b;
    uint16_t *OH, *OL, *UH, *UL, *WHp, *WLp;
    int *Cnt, *Rs, *Tarr;
    unsigned char *Fi, *Fj;
    cudaGetSymbolAddress((void**)&X,    g_X);
    cudaGetSymbolAddress((void**)&QKV,  g_QKV);
    cudaGetSymbolAddress((void**)&BQKV, g_bqkv);
    cudaGetSymbolAddress((void**)&A8a,  g_A8a);
    cudaGetSymbolAddress((void**)&A8b,  g_A8b);
    cudaGetSymbolAddress((void**)&SA,   g_sA);
    cudaGetSymbolAddress((void**)&W8a,  g_W8a);
    cudaGetSymbolAddress((void**)&W8b,  g_W8b);
    cudaGetSymbolAddress((void**)&SW,   g_sW);
    cudaGetSymbolAddress((void**)&OH,   g_OH);
    cudaGetSymbolAddress((void**)&OL,   g_OL);
    cudaGetSymbolAddress((void**)&UH,   g_UH);
    cudaGetSymbolAddress((void**)&UL,   g_UL);
    cudaGetSymbolAddress((void**)&WHp,  g_WH);
    cudaGetSymbolAddress((void**)&WLp,  g_WL);
    cudaGetSymbolAddress((void**)&Cnt,  g_cnt);
    cudaGetSymbolAddress((void**)&Rs,   g_rs);
    cudaGetSymbolAddress((void**)&Fi,   g_fi);
    cudaGetSymbolAddress((void**)&Fj,   g_fj);
    cudaGetSymbolAddress((void**)&Tarr, g_T);

    cudaFuncSetAttribute(gemm_kernel<EPI_RES>,
                         cudaFuncAttributeMaxDynamicSharedMemorySize, (int)GEMM_SMEM);
    cudaFuncSetAttribute(gemm8_kernel<EPI_PLAIN>,
                         cudaFuncAttributeMaxDynamicSharedMemorySize, (int)GEMM8_SMEM);
    cudaFuncSetAttribute(gemm8_kernel<EPI_REGLU>,
                         cudaFuncAttributeMaxDynamicSharedMemorySize, (int)GEMM8_SMEM);

    mask_convert_kernel<<<(L * S * S + 255) / 256, 256>>>(mask_raw);
    csr_build_kernel<<<1, 32>>>();
    biaspack_kernel<<<(L * NQKV + 255) / 256, 256>>>(bq, bk, bv);
    tokenize_kernel<<<(M * (D / 4) + 255) / 256, 256>>>(
        x_num, x_cat, w_num, b_num, emb_cat, b_cat, cls, cat_offsets);
    {
        size_t t16 = L * W16_LSTR / 4;
        wsplit16_kernel<<<(unsigned)((t16 + 255) / 256), 256>>>(Wo, Wf2);
        wcolscale_kernel<<<(L * W8N + 7) / 8, 256>>>(Wq, Wk, Wv, Wf1);
        size_t t8 = W8_TOT / 4;
        wsplit8_kernel<<<(unsigned)((t8 + 255) / 256), 256>>>(Wq, Wk, Wv, Wf1);
    }

    const dim3 gQKV8(M / 128, NQKV / 64);       // int8, N=1536
    const dim3 gF18(M / 128, (2 * FH) / 64);    // int8, N=2048 interleaved
    const dim3 g512(M / 128, D / 128);          // bf16, N=512

    for (int l = 0; l < L; ++l) {
        size_t lo16 = (size_t)l * W16_LSTR;
        size_t lo8  = (size_t)l * W8N * D;
        const float* sWl = SW + (size_t)l * W8N;

        ln_quant_kernel<<<M / 8, 256>>>(X, ln1_w + (size_t)l * D, ln1_b + (size_t)l * D);

        gemm8_kernel<EPI_PLAIN><<<gQKV8, 256, GEMM8_SMEM>>>(
            A8a, A8b, SA, W8a + lo8, W8b + lo8, sWl,
            BQKV + l * NQKV, QKV, nullptr, nullptr, NQKV);

        attn_kernel<<<B * NH, 256>>>(QKV, Cnt + l * S, Rs + l * S,
            Fi + l * S * S, Fj + l * S * S, Tarr + l, OH, OL);

        gemm_kernel<EPI_RES><<<g512, 256, GEMM_SMEM>>>(OH, OL, WHp + lo16, WLp + lo16,
            bo + (size_t)l * D, X, X, D, D);

        ln_quant_kernel<<<M / 8, 256>>>(X, ln2_w + (size_t)l * D, ln2_b + (size_t)l * D);

        gemm8_kernel<EPI_REGLU><<<gF18, 256, GEMM8_SMEM>>>(
            A8a, A8b, SA, W8a + lo8 + (size_t)OFF8_F1 * D, W8b + lo8 + (size_t)OFF8_F1 * D,
            sWl + OFF8_F1, bf1 + (size_t)l * 2 * FH, nullptr, UH, UL, 2 * FH);

        gemm_kernel<EPI_RES><<<g512, 256, GEMM_SMEM>>>(UH, UL,
            WHp + lo16 + OFF16_F2, WLp + lo16 + OFF16_F2,
            bf2 + (size_t)l * D, X, X, FH, D);
    }

    head_kernel<<<B, 128>>>(X, hln_w, hln_b, Wh, bh, out);
}

// round 13
// speedup vs baseline: 1.9374x; 1.9374x over previous
#include <cuda_runtime.h>
#include <cuda_bf16.h>
#include <cstdint>

// ---------------- problem constants ----------------
namespace {
constexpr int B   = 2048;
constexpr int NN  = 24;
constexpr int NC  = 8;
constexpr int D   = 512;
constexpr int NH  = 8;     // heads
constexpr int L   = 3;
constexpr int FH  = 1024;
constexpr int S   = 33;    // NN + NC + 1
constexpr int DH  = 64;    // D / NH
constexpr int M   = B * S; // 67584 rows; divisible by 128
constexpr int NQKV = 3 * D; // 1536 packed QKV width

// weight plane layout (bf16 hi/lo), per-layer: QKV[512][1536] | O[512][512] | F1[512][2048 interleaved] | F2[1024][512]
constexpr size_t W_QKV  = (size_t)D * NQKV;
constexpr size_t W_O    = (size_t)D * D;
constexpr size_t W_F1   = (size_t)D * (2 * FH);
constexpr size_t W_F2   = (size_t)FH * D;
constexpr size_t OFF_O  = W_QKV;
constexpr size_t OFF_F1 = W_QKV + W_O;
constexpr size_t OFF_F2 = W_QKV + W_O + W_F1;
constexpr size_t W_LSTR = W_QKV + W_O + W_F1 + W_F2;   // 2621440
constexpr size_t W_TOT  = 3 * W_LSTR;

// GEMM smem geometry (bf16 elements), BM=128 BN=128 BK=32, 3 stages
constexpr int A_STRIDE = 40;               // 80B rows -> ldmatrix conflict-free
constexpr int B_STRIDE = 136;              // 272B rows -> ldmatrix.trans conflict-free
constexpr int A_PLANE  = 128 * A_STRIDE;   // 5120 elems
constexpr int B_PLANE  = 32 * B_STRIDE;    // 4352 elems
constexpr uint32_t ST_AL = (uint32_t)A_PLANE * 2;
constexpr uint32_t ST_BH = 2u * A_PLANE * 2;
constexpr uint32_t ST_BL = 2u * A_PLANE * 2 + B_PLANE * 2;
constexpr uint32_t STAGE_BYTES = 2u * (A_PLANE + B_PLANE) * 2; // 37888
constexpr size_t GEMM_SMEM = 3 * (size_t)STAGE_BYTES;          // 113664

constexpr int EPI_PLAIN = 0;
constexpr int EPI_RES   = 1;
constexpr int EPI_REGLU = 2;
}

// ---------------- scratch (device globals; allocation-free) ----------------
__device__ float g_X[(size_t)M * D];            // residual stream (fp32)
__device__ float g_QKV[(size_t)M * NQKV];       // packed Q|K|V (fp32)
__device__ float g_bqkv[L * NQKV];              // packed qkv bias
__device__ uint16_t g_HnH[(size_t)M * D];       // LN out hi/lo bf16 planes
__device__ uint16_t g_HnL[(size_t)M * D];
__device__ uint16_t g_OH[(size_t)M * D];        // attn out planes
__device__ uint16_t g_OL[(size_t)M * D];
__device__ uint16_t g_UH[(size_t)M * FH];       // reglu out planes
__device__ uint16_t g_UL[(size_t)M * FH];
__device__ uint16_t g_WH[W_TOT];                // weight planes
__device__ uint16_t g_WL[W_TOT];
// sparse-mask CSR (per layer)
__device__ int g_cnt[L * S];
__device__ int g_rs[L * S];
__device__ unsigned char g_fi[L * S * S];
__device__ unsigned char g_fj[L * S * S];
__device__ int g_T[L];

// ---------------- helpers ----------------
__device__ __forceinline__ void split2(float x, float y, uint32_t& hi, uint32_t& lo)
{
    __nv_bfloat162 h = __floats2bfloat162_rn(x, y);
    float hx = __bfloat162float(h.x), hy = __bfloat162float(h.y);
    __nv_bfloat162 l = __floats2bfloat162_rn(x - hx, y - hy);
    hi = *reinterpret_cast<uint32_t*>(&h);
    lo = *reinterpret_cast<uint32_t*>(&l);
}

__device__ __forceinline__ void split1(float x, uint16_t& hi, uint16_t& lo)
{
    __nv_bfloat16 h = __float2bfloat16(x);
    float hf = __bfloat162float(h);
    __nv_bfloat16 l = __float2bfloat16(x - hf);
    hi = *reinterpret_cast<uint16_t*>(&h);
    lo = *reinterpret_cast<uint16_t*>(&l);
}

__device__ __forceinline__ void ldmx4(uint32_t addr, uint32_t& r0, uint32_t& r1,
                                      uint32_t& r2, uint32_t& r3)
{
    asm volatile("ldmatrix.sync.aligned.m8n8.x4.shared.b16 {%0,%1,%2,%3},[%4];"
                 : "=r"(r0), "=r"(r1), "=r"(r2), "=r"(r3) : "r"(addr));
}

__device__ __forceinline__ void ldmx4t(uint32_t addr, uint32_t& r0, uint32_t& r1,
                                       uint32_t& r2, uint32_t& r3)
{
    asm volatile("ldmatrix.sync.aligned.m8n8.x4.trans.shared.b16 {%0,%1,%2,%3},[%4];"
                 : "=r"(r0), "=r"(r1), "=r"(r2), "=r"(r3) : "r"(addr));
}

__device__ __forceinline__ void mma16(float* c, const uint32_t* a, const uint32_t* b)
{
    asm volatile(
        "mma.sync.aligned.m16n8k16.row.col.f32.bf16.bf16.f32 "
        "{%0,%1,%2,%3},{%4,%5,%6,%7},{%8,%9},{%0,%1,%2,%3};\n"
        : "+f"(c[0]), "+f"(c[1]), "+f"(c[2]), "+f"(c[3])
        : "r"(a[0]), "r"(a[1]), "r"(a[2]), "r"(a[3]),
          "r"(b[0]), "r"(b[1]));
}

__device__ __forceinline__ void cpasync16(uint32_t dst, const void* src) {
    asm volatile("cp.async.cg.shared.global [%0], [%1], 16;" :: "r"(dst), "l"(src));
}

// ---------------- CSR build (includes mask dtype canonicalization) ----------------
// raw mask may be uint8/bool, float32, or int32; detect layout from invariants
// (element 34 = m[l=0][1][1] is always True: as uint8 byte 34 == 1; as
// int32/float32 byte 34 is byte-2 of element 8, 0 or 0x80, never 1; float32
// detected by exponent byte of element 0 == 0x3f). Ascending j preserves the
// reference's fp summation order.
__global__ void csr_build_kernel(const unsigned char* __restrict__ raw)
{
    int l = threadIdx.x;
    if (l >= L) return;
    const int mode = (raw[34] == 1) ? 0 : (raw[3] == 0x3f) ? 1 : 2;
    int pos = 0;
    for (int i = 0; i < S; ++i) {
        g_rs[l * S + i] = pos;
        int c = 0;
        for (int j = 0; j < S; ++j) {
            int idx = l * S * S + i * S + j;
            bool v;
            if (mode == 0)      v = raw[idx] != 0;
            else if (mode == 1) v = ((const float*)raw)[idx] != 0.0f;
            else                v = ((const int*)raw)[idx] != 0;
            if (v) {
                g_fi[l * S * S + pos] = (unsigned char)i;
                g_fj[l * S * S + pos] = (unsigned char)j;
                ++pos; ++c;
            }
        }
        g_cnt[l * S + i] = c;
    }
    g_T[l] = pos;
}

// ---------------- qkv bias pack ----------------
__global__ void biaspack_kernel(const float* __restrict__ bq, const float* __restrict__ bk,
                                const float* __restrict__ bv)
{
    int i = blockIdx.x * blockDim.x + threadIdx.x;
    if (i >= L * NQKV) return;
    int l = i / NQKV, c = i % NQKV;
    float v = (c < D) ? bq[l * D + c] : (c < 2 * D) ? bk[l * D + c - D] : bv[l * D + c - 2 * D];
    g_bqkv[i] = v;
}

// ---------------- tokenizer ----------------
__global__ void tokenize_kernel(const float* __restrict__ x_num,
                                const int* __restrict__ x_cat,
                                const float* __restrict__ w_num,
                                const float* __restrict__ b_num,
                                const float* __restrict__ emb_cat,
                                const float* __restrict__ b_cat,
                                const float* __restrict__ cls,
                                const int* __restrict__ cat_offsets)
{
    int idx = blockIdx.x * blockDim.x + threadIdx.x;
    const int total = M * (D / 4);
    if (idx >= total) return;
    int d4 = idx & (D / 4 - 1);
    int ms = idx >> 7;
    int s  = ms % S;
    int b  = ms / S;
    int d  = d4 * 4;
    float4 o;
    if (s < NN) {
        float xv  = x_num[b * NN + s];
        float4 w  = *(const float4*)(w_num + (size_t)s * D + d);
        float4 bb = *(const float4*)(b_num + (size_t)s * D + d);
        o.x = xv * w.x + bb.x;
        o.y = xv * w.y + bb.y;
        o.z = xv * w.z + bb.z;
        o.w = xv * w.w + bb.w;
    } else if (s < NN + NC) {
        int c   = s - NN;
        int row = x_cat[b * NC + c] + cat_offsets[c];
        float4 e  = *(const float4*)(emb_cat + (size_t)row * D + d);
        float4 bb = *(const float4*)(b_cat + (size_t)c * D + d);
        o.x = e.x + bb.x; o.y = e.y + bb.y; o.z = e.z + bb.z; o.w = e.w + bb.w;
    } else {
        o = *(const float4*)(cls + d);
    }
    *(float4*)(g_X + (size_t)ms * D + d) = o;
}

// ---------------- mega weight split: ALL layers, ALL weights, one launch ----------------
__global__ void wsplit_mega_kernel(const float* __restrict__ Wq, const float* __restrict__ Wk,
                                   const float* __restrict__ Wv, const float* __restrict__ Wo,
                                   const float* __restrict__ Wf1, const float* __restrict__ Wf2)
{
    size_t idx = (size_t)blockIdx.x * blockDim.x + threadIdx.x;
    const size_t total = L * W_LSTR / 4;
    if (idx >= total) return;
    size_t d0 = idx * 4;
    int l = (int)(d0 / W_LSTR);
    size_t o = d0 - (size_t)l * W_LSTR;

    float v[4];
    if (o < W_QKV) {
        int k = (int)(o / NQKV);
        int n = (int)(o % NQKV);
        const float* src = (n < D) ? Wq : (n < 2 * D) ? Wk : Wv;
        float4 vv = *(const float4*)(src + ((size_t)l * D + k) * D + (n & (D - 1)));
        v[0] = vv.x; v[1] = vv.y; v[2] = vv.z; v[3] = vv.w;
    } else if (o < OFF_F1) {
        size_t oo = o - OFF_O;
        int k = (int)(oo / D), n = (int)(oo % D);
        float4 vv = *(const float4*)(Wo + ((size_t)l * D + k) * D + n);
        v[0] = vv.x; v[1] = vv.y; v[2] = vv.z; v[3] = vv.w;
    } else if (o < OFF_F2) {
        size_t oo = o - OFF_F1;
        int k = (int)(oo / (2 * FH));
        int c = (int)(oo % (2 * FH));        // quad-aligned, even
        int j = c >> 1;
        const float* row = Wf1 + ((size_t)l * D + k) * (2 * FH);
        v[0] = row[j];          v[1] = row[FH + j];
        v[2] = row[j + 1];      v[3] = row[FH + j + 1];
    } else {
        size_t oo = o - OFF_F2;
        int k = (int)(oo / D), n = (int)(oo % D);
        float4 vv = *(const float4*)(Wf2 + ((size_t)l * FH + k) * D + n);
        v[0] = vv.x; v[1] = vv.y; v[2] = vv.z; v[3] = vv.w;
    }

    uint32_t h0, l0, h1, l1;
    split2(v[0], v[1], h0, l0);
    split2(v[2], v[3], h1, l1);
    *(uint2*)(g_WH + d0) = make_uint2(h0, h1);
    *(uint2*)(g_WL + d0) = make_uint2(l0, l1);
}

// ---------------- LayerNorm (warp per row) -> hi/lo bf16 planes ----------------
__global__ void ln_split_kernel(const float* __restrict__ X,
                                uint16_t* __restrict__ YH, uint16_t* __restrict__ YL,
                                const float* __restrict__ w, const float* __restrict__ bb)
{
    int warp = threadIdx.x >> 5;
    int lane = threadIdx.x & 31;
    int row  = blockIdx.x * 8 + warp;
    const float* xr = X + (size_t)row * D;
    float4 v[4];
    float s = 0.0f, sq = 0.0f;
#pragma unroll
    for (int c = 0; c < 4; ++c) {
        v[c] = *(const float4*)(xr + c * 128 + lane * 4);
        s  += v[c].x + v[c].y + v[c].z + v[c].w;
        sq += v[c].x * v[c].x + v[c].y * v[c].y + v[c].z * v[c].z + v[c].w * v[c].w;
    }
#pragma unroll
    for (int o = 16; o > 0; o >>= 1) {
        s  += __shfl_xor_sync(0xffffffffu, s, o);
        sq += __shfl_xor_sync(0xffffffffu, sq, o);
    }
    float mean = s * (1.0f / D);
    float var  = sq * (1.0f / D) - mean * mean;
    float r = rsqrtf(var + 1e-5f);
#pragma unroll
    for (int c = 0; c < 4; ++c) {
        int col = c * 128 + lane * 4;
        float4 wv = *(const float4*)(w + col);
        float4 bv = *(const float4*)(bb + col);
        float4 o;
        o.x = (v[c].x - mean) * r * wv.x + bv.x;
        o.y = (v[c].y - mean) * r * wv.y + bv.y;
        o.z = (v[c].z - mean) * r * wv.z + bv.z;
        o.w = (v[c].w - mean) * r * wv.w + bv.w;
        uint32_t h0, l0, h1, l1;
        split2(o.x, o.y, h0, l0);
        split2(o.z, o.w, h1, l1);
        size_t off = (size_t)row * D + col;
        *(uint2*)(YH + off) = make_uint2(h0, h1);
        *(uint2*)(YL + off) = make_uint2(l0, l1);
    }
}

// ---------------- split-bf16 3-term tensor-core GEMM, 3-stage cp.async ----------------
template <int EPI>
__global__ void __launch_bounds__(256, 2)
gemm_kernel(const uint16_t* __restrict__ AH, const uint16_t* __restrict__ AL,
            const uint16_t* __restrict__ BH, const uint16_t* __restrict__ BL,
            const float* __restrict__ bias, const float* __restrict__ Rsd,
            float* __restrict__ C, uint16_t* __restrict__ UH, uint16_t* __restrict__ UL,
            int K, int N)
{
    extern __shared__ uint16_t sm[];
    const uint32_t shBase = (uint32_t)__cvta_generic_to_shared(sm);

    const int tid  = threadIdx.x;
    const int lane = tid & 31;
    const int warp = tid >> 5;
    const int wm   = (warp & 1) * 64;
    const int wn   = (warp >> 1) * 32;
    const int grp  = lane >> 2;
    const int t4   = lane & 3;

    const int bm = blockIdx.x;
    const int bn = blockIdx.y;
    const int KT = K >> 5;

    float acc[4][4][4];
#pragma unroll
    for (int i = 0; i < 4; ++i)
#pragma unroll
        for (int j = 0; j < 4; ++j)
#pragma unroll
            for (int r = 0; r < 4; ++r) acc[i][j][r] = 0.0f;

    const int agr = tid >> 1;
    const int aco = (tid & 1) * 32;
    const int bgr = tid >> 3;
    const int bco = (tid & 7) * 32;

    auto load_tile = [&](int kt, int st) {
        const uint32_t sb = shBase + (uint32_t)st * STAGE_BYTES;
        {
            uint32_t doff = sb + (uint32_t)(agr * A_STRIDE) * 2 + aco;
            const uint16_t* sH = AH + (size_t)(bm * 128 + agr) * K + kt * 32 + (aco >> 1);
            const uint16_t* sL = AL + (size_t)(bm * 128 + agr) * K + kt * 32 + (aco >> 1);
            cpasync16(doff,               sH);
            cpasync16(doff + 16,          sH + 8);
            cpasync16(doff + ST_AL,       sL);
            cpasync16(doff + ST_AL + 16,  sL + 8);
        }
        {
            uint32_t doff = sb + ST_BH + (uint32_t)(bgr * B_STRIDE) * 2 + bco;
            const uint16_t* sH = BH + (size_t)(kt * 32 + bgr) * N + bn * 128 + (bco >> 1);
            const uint16_t* sL = BL + (size_t)(kt * 32 + bgr) * N + bn * 128 + (bco >> 1);
            cpasync16(doff,                         sH);
            cpasync16(doff + 16,                    sH + 8);
            cpasync16(doff + (ST_BL - ST_BH),       sL);
            cpasync16(doff + (ST_BL - ST_BH) + 16,  sL + 8);
        }
        asm volatile("cp.async.commit_group;" ::: "memory");
    };

    const int arowL = lane & 15;
    const int kofA  = (lane >> 4) * 8;
    const uint32_t aBase = shBase + (uint32_t)(((wm + arowL) * A_STRIDE + kofA) * 2);
    const int krowL = lane & 15;
    const int nofB  = (lane >> 4) * 8;
    const uint32_t bBase = shBase + ST_BH + (uint32_t)((krowL * B_STRIDE + wn + nofB) * 2);

    load_tile(0, 0);
    load_tile(1, 1);

    for (int kt = 0; kt < KT; ++kt) {
        const int st = kt % 3;
        if (kt + 1 < KT) asm volatile("cp.async.wait_group 1;" ::: "memory");
        else             asm volatile("cp.async.wait_group 0;" ::: "memory");
        __syncthreads();
        if (kt + 2 < KT) load_tile(kt + 2, (kt + 2) % 3);

        const uint32_t aSt = aBase + (uint32_t)st * STAGE_BYTES;
        const uint32_t bSt = bBase + (uint32_t)st * STAGE_BYTES;
#pragma unroll
        for (int ks = 0; ks < 2; ++ks) {
            uint32_t ah[4][4], al[4][4];
#pragma unroll
            for (int mi = 0; mi < 4; ++mi) {
                uint32_t ad = aSt + mi * (16 * A_STRIDE * 2) + ks * 32;
                ldmx4(ad, ah[mi][0], ah[mi][1], ah[mi][2], ah[mi][3]);
                ldmx4(ad + ST_AL, al[mi][0], al[mi][1], al[mi][2], al[mi][3]);
            }
#pragma unroll
            for (int pr = 0; pr < 2; ++pr) {
                uint32_t bh[2][2], bl[2][2];
                uint32_t bd = bSt + pr * 32 + ks * (16 * B_STRIDE * 2);
                ldmx4t(bd, bh[0][0], bh[0][1], bh[1][0], bh[1][1]);
                ldmx4t(bd + (ST_BL - ST_BH), bl[0][0], bl[0][1], bl[1][0], bl[1][1]);
#pragma unroll
                for (int mi = 0; mi < 4; ++mi)
#pragma unroll
                    for (int nj = 0; nj < 2; ++nj)
                        mma16(acc[mi][2 * pr + nj], al[mi], bh[nj]);
#pragma unroll
                for (int mi = 0; mi < 4; ++mi)
#pragma unroll
                    for (int nj = 0; nj < 2; ++nj)
                        mma16(acc[mi][2 * pr + nj], ah[mi], bl[nj]);
#pragma unroll
                for (int mi = 0; mi < 4; ++mi)
#pragma unroll
                    for (int nj = 0; nj < 2; ++nj)
                        mma16(acc[mi][2 * pr + nj], ah[mi], bh[nj]);
            }
        }
    }

    // epilogue
#pragma unroll
    for (int mi = 0; mi < 4; ++mi) {
        int r0 = bm * 128 + wm + mi * 16 + grp;
#pragma unroll
        for (int ni = 0; ni < 4; ++ni) {
            int c0 = bn * 128 + wn + ni * 8 + 2 * t4;
            if (EPI == EPI_REGLU) {
                int j = c0 >> 1;
                float ba = bias[j], bg = bias[FH + j];
                float u0 = (acc[mi][ni][0] + ba) * fmaxf(acc[mi][ni][1] + bg, 0.0f);
                float u1 = (acc[mi][ni][2] + ba) * fmaxf(acc[mi][ni][3] + bg, 0.0f);
                uint16_t h, l;
                split1(u0, h, l);
                UH[(size_t)r0 * FH + j] = h;
                UL[(size_t)r0 * FH + j] = l;
                split1(u1, h, l);
                UH[(size_t)(r0 + 8) * FH + j] = h;
                UL[(size_t)(r0 + 8) * FH + j] = l;
            } else {
                float b0 = bias[c0], b1 = bias[c0 + 1];
                float2 o0 = make_float2(acc[mi][ni][0] + b0, acc[mi][ni][1] + b1);
                float2 o1 = make_float2(acc[mi][ni][2] + b0, acc[mi][ni][3] + b1);
                if (EPI == EPI_RES) {
                    float2 rv0 = *(const float2*)(Rsd + (size_t)r0 * N + c0);
                    float2 rv1 = *(const float2*)(Rsd + (size_t)(r0 + 8) * N + c0);
                    o0.x += rv0.x; o0.y += rv0.y;
                    o1.x += rv1.x; o1.y += rv1.y;
                }
                *(float2*)(C + (size_t)r0 * N + c0)       = o0;
                *(float2*)(C + (size_t)(r0 + 8) * N + c0) = o1;
            }
        }
    }
}

// ---------------- sparse attention (one block per (batch, head); CSR mask) ----------------
// Masked entries contribute exactly 0.0f in the reference (expf underflow), and
// x + 0.0f == x, so skipping them in ascending-j order is bit-identical.
__global__ void attn_kernel(const float* __restrict__ QKV,
                            const int* __restrict__ cnt, const int* __restrict__ rs,
                            const unsigned char* __restrict__ fi,
                            const unsigned char* __restrict__ fj,
                            const int* __restrict__ Tp,
                            uint16_t* __restrict__ OH, uint16_t* __restrict__ OL)
{
    int bh = blockIdx.x;
    int h  = bh % NH;
    int b  = bh / NH;
    int t  = threadIdx.x;   // 256

    __shared__ float qs[S][DH + 1];
    __shared__ float ks[S][DH + 1];
    __shared__ float vs[S][DH + 1];
    __shared__ float fp[S * S];
    __shared__ unsigned char sfi[S * S], sfj[S * S];
    __shared__ int scnt[S], srs[S];

    const int T = *Tp;

    const size_t rbase = (size_t)(b * S) * NQKV + h * DH;
    for (int i = t; i < S * DH; i += 256) {
        int s = i / DH, d = i % DH;
        size_t p = rbase + (size_t)s * NQKV + d;
        qs[s][d] = QKV[p];
        ks[s][d] = QKV[p + D];
        vs[s][d] = QKV[p + 2 * D];
    }
    for (int p = t; p < T; p += 256) { sfi[p] = fi[p]; sfj[p] = fj[p]; }
    if (t < S) { scnt[t] = cnt[t]; srs[t] = rs[t]; }
    __syncthreads();

    const float scale = 0.125f;  // 1/sqrt(64)
    for (int p = t; p < T; p += 256) {
        int i = sfi[p], j = sfj[p];
        float s = 0.0f;
#pragma unroll 16
        for (int d = 0; d < DH; ++d) s += qs[i][d] * ks[j][d];
        fp[p] = s * scale;
    }
    __syncthreads();

    if (t < S) {
        int r0 = srs[t], c = scnt[t];
        float mx = -1e30f;
        for (int e = 0; e < c; ++e) mx = fmaxf(mx, fp[r0 + e]);
        float sum = 0.0f;
        for (int e = 0; e < c; ++e) { float ee = __expf(fp[r0 + e] - mx); fp[r0 + e] = ee; sum += ee; }
        float inv = 1.0f / sum;
        for (int e = 0; e < c; ++e) fp[r0 + e] *= inv;
    }
    __syncthreads();

    const size_t obase = (size_t)(b * S) * D + h * DH;
    for (int p = t; p < S * (DH / 2); p += 256) {
        int i  = p / (DH / 2);
        int dd = (p % (DH / 2)) * 2;
        int r0 = srs[i], c = scnt[i];
        float o0 = 0.0f, o1 = 0.0f;
        for (int e = 0; e < c; ++e) {
            int j = sfj[r0 + e];
            float a = fp[r0 + e];
            o0 += a * vs[j][dd];
            o1 += a * vs[j][dd + 1];
        }
        uint32_t hi, lo;
        split2(o0, o1, hi, lo);
        size_t off = obase + (size_t)i * D + dd;
        *(uint32_t*)(OH + off) = hi;
        *(uint32_t*)(OL + off) = lo;
    }
}

// ---------------- head: LN(cls) -> relu -> dot Wh + bh ----------------
__global__ void head_kernel(const float* __restrict__ X,
                            const float* __restrict__ hw, const float* __restrict__ hb,
                            const float* __restrict__ Wh, const float* __restrict__ bh,
                            float* __restrict__ out)
{
    int b = blockIdx.x;
    int t = threadIdx.x;   // 128
    const float* xr = X + ((size_t)b * S + (S - 1)) * D;
    float4 v = *(const float4*)(xr + t * 4);
    float s  = v.x + v.y + v.z + v.w;
    float sq = v.x * v.x + v.y * v.y + v.z * v.z + v.w * v.w;
#pragma unroll
    for (int o = 16; o > 0; o >>= 1) {
        s  += __shfl_xor_sync(0xffffffffu, s, o);
        sq += __shfl_xor_sync(0xffffffffu, sq, o);
    }
    __shared__ float ss[4], sqs[4], ds[4];
    if ((t & 31) == 0) { ss[t >> 5] = s; sqs[t >> 5] = sq; }
    __syncthreads();
    s  = ss[0] + ss[1] + ss[2] + ss[3];
    sq = sqs[0] + sqs[1] + sqs[2] + sqs[3];
    float mean = s * (1.0f / D);
    float var  = sq * (1.0f / D) - mean * mean;
    float r = rsqrtf(var + 1e-5f);
    float4 wv = *(const float4*)(hw + t * 4);
    float4 bv = *(const float4*)(hb + t * 4);
    float4 wh = *(const float4*)(Wh + t * 4);   // DOUT == 1
    float dot = 0.0f;
    dot += fmaxf((v.x - mean) * r * wv.x + bv.x, 0.0f) * wh.x;
    dot += fmaxf((v.y - mean) * r * wv.y + bv.y, 0.0f) * wh.y;
    dot += fmaxf((v.z - mean) * r * wv.z + bv.z, 0.0f) * wh.z;
    dot += fmaxf((v.w - mean) * r * wv.w + bv.w, 0.0f) * wh.w;
#pragma unroll
    for (int o = 16; o > 0; o >>= 1) dot += __shfl_xor_sync(0xffffffffu, dot, o);
    if ((t & 31) == 0) ds[t >> 5] = dot;
    __syncthreads();
    if (t == 0) out[b] = ds[0] + ds[1] + ds[2] + ds[3] + bh[0];
}

// ---------------- launcher ----------------
extern "C" void kernel_launch(void* const* d_in, const int* in_sizes, int n_in,
                              void* d_out, int out_size)
{
    (void)in_sizes; (void)n_in; (void)out_size;
    const float* x_num    = (const float*)d_in[0];
    const int*   x_cat    = (const int*)d_in[1];
    const float* w_num    = (const float*)d_in[2];
    const float* b_num    = (const float*)d_in[3];
    const float* emb_cat  = (const float*)d_in[4];
    const float* b_cat    = (const float*)d_in[5];
    const float* cls      = (const float*)d_in[6];
    const float* ln1_w    = (const float*)d_in[7];
    const float* ln1_b    = (const float*)d_in[8];
    const float* Wq       = (const float*)d_in[9];
    const float* bq       = (const float*)d_in[10];
    const float* Wk       = (const float*)d_in[11];
    const float* bk       = (const float*)d_in[12];
    const float* Wv       = (const float*)d_in[13];
    const float* bv       = (const float*)d_in[14];
    const float* Wo       = (const float*)d_in[15];
    const float* bo       = (const float*)d_in[16];
    const float* ln2_w    = (const float*)d_in[17];
    const float* ln2_b    = (const float*)d_in[18];
    const float* Wf1      = (const float*)d_in[19];
    const float* bf1      = (const float*)d_in[20];
    const float* Wf2      = (const float*)d_in[21];
    const float* bf2      = (const float*)d_in[22];
    const unsigned char* mask_raw = (const unsigned char*)d_in[23];
    const int*   cat_offsets  = (const int*)d_in[24];
    const float* hln_w    = (const float*)d_in[25];
    const float* hln_b    = (const float*)d_in[26];
    const float* Wh       = (const float*)d_in[27];
    const float* bh       = (const float*)d_in[28];
    float* out = (float*)d_out;

    float *X, *QKV, *BQKV;
    uint16_t *HnH, *HnL, *OH, *OL, *UH, *UL, *WHp, *WLp;
    int *Cnt, *Rs, *Tarr;
    unsigned char *Fi, *Fj;
    cudaGetSymbolAddress((void**)&X,    g_X);
    cudaGetSymbolAddress((void**)&QKV,  g_QKV);
    cudaGetSymbolAddress((void**)&BQKV, g_bqkv);
    cudaGetSymbolAddress((void**)&HnH,  g_HnH);
    cudaGetSymbolAddress((void**)&HnL,  g_HnL);
    cudaGetSymbolAddress((void**)&OH,   g_OH);
    cudaGetSymbolAddress((void**)&OL,   g_OL);
    cudaGetSymbolAddress((void**)&UH,   g_UH);
    cudaGetSymbolAddress((void**)&UL,   g_UL);
    cudaGetSymbolAddress((void**)&WHp,  g_WH);
    cudaGetSymbolAddress((void**)&WLp,  g_WL);
    cudaGetSymbolAddress((void**)&Cnt,  g_cnt);
    cudaGetSymbolAddress((void**)&Rs,   g_rs);
    cudaGetSymbolAddress((void**)&Fi,   g_fi);
    cudaGetSymbolAddress((void**)&Fj,   g_fj);
    cudaGetSymbolAddress((void**)&Tarr, g_T);

    cudaFuncSetAttribute(gemm_kernel<EPI_PLAIN>,
                         cudaFuncAttributeMaxDynamicSharedMemorySize, (int)GEMM_SMEM);
    cudaFuncSetAttribute(gemm_kernel<EPI_RES>,
                         cudaFuncAttributeMaxDynamicSharedMemorySize, (int)GEMM_SMEM);
    cudaFuncSetAttribute(gemm_kernel<EPI_REGLU>,
                         cudaFuncAttributeMaxDynamicSharedMemorySize, (int)GEMM_SMEM);

    // prologue: 4 launches, so launch #6 (ncu -s 5 -c 1 capture) = QKV GEMM
    csr_build_kernel<<<1, 32>>>(mask_raw);                                           // 1
    biaspack_kernel<<<(L * NQKV + 255) / 256, 256>>>(bq, bk, bv);                    // 2
    tokenize_kernel<<<(M * (D / 4) + 255) / 256, 256>>>(                             // 3
        x_num, x_cat, w_num, b_num, emb_cat, b_cat, cls, cat_offsets);
    {
        size_t total = L * W_LSTR / 4;
        wsplit_mega_kernel<<<(unsigned)((total + 255) / 256), 256>>>(                // 4
            Wq, Wk, Wv, Wo, Wf1, Wf2);
    }

    const dim3 gQKV(M / 128, NQKV / 128);       // N = 1536
    const dim3 g512(M / 128, D / 128);          // N = 512
    const dim3 g2048(M / 128, (2 * FH) / 128);  // N = 2048 (interleaved a/g)

    for (int l = 0; l < L; ++l) {
        size_t lo = (size_t)l * W_LSTR;
        ln_split_kernel<<<M / 8, 256>>>(X, HnH, HnL, ln1_w + (size_t)l * D, ln1_b + (size_t)l * D);  // 5

        gemm_kernel<EPI_PLAIN><<<gQKV, 256, GEMM_SMEM>>>(HnH, HnL, WHp + lo, WLp + lo,               // 6 <- ncu
            BQKV + l * NQKV, nullptr, QKV, nullptr, nullptr, D, NQKV);

        attn_kernel<<<B * NH, 256>>>(QKV, Cnt + l * S, Rs + l * S,
            Fi + l * S * S, Fj + l * S * S, Tarr + l, OH, OL);

        gemm_kernel<EPI_RES><<<g512, 256, GEMM_SMEM>>>(OH, OL, WHp + lo + OFF_O, WLp + lo + OFF_O,
            bo + (size_t)l * D, X, X, nullptr, nullptr, D, D);

        ln_split_kernel<<<M / 8, 256>>>(X, HnH, HnL, ln2_w + (size_t)l * D, ln2_b + (size_t)l * D);

        gemm_kernel<EPI_REGLU><<<g2048, 256, GEMM_SMEM>>>(HnH, HnL, WHp + lo + OFF_F1, WLp + lo + OFF_F1,
            bf1 + (size_t)l * 2 * FH, nullptr, nullptr, UH, UL, D, 2 * FH);

        gemm_kernel<EPI_RES><<<g512, 256, GEMM_SMEM>>>(UH, UL, WHp + lo + OFF_F2, WLp + lo + OFF_F2,
            bf2 + (size_t)l * D, X, X, nullptr, nullptr, FH, D);
    }

    head_kernel<<<B, 128>>>(X, hln_w, hln_b, Wh, bh, out);
}